// round 1
// baseline (speedup 1.0000x reference)
#include <cuda_runtime.h>

#define KC 1024
#define DC 64
#define NV 131072
#define TM 128      // rows per block
#define TKC 128     // codes per chunk

// scratch (allocation-free: __device__ globals)
__device__ float g_esq[KC];
__device__ float g_counts[KC];
__device__ float g_sums[KC * DC];
__device__ float g_loss[1];

__device__ __forceinline__ void fma2(unsigned long long &acc, unsigned long long a,
                                     unsigned long long b) {
    asm("fma.rn.f32x2 %0, %1, %2, %0;" : "+l"(acc) : "l"(a), "l"(b));
}
__device__ __forceinline__ unsigned long long pack2(float lo, float hi) {
    unsigned long long r;
    asm("mov.b64 %0, {%1, %2};" : "=l"(r) : "f"(lo), "f"(hi));
    return r;
}
__device__ __forceinline__ float2 unpack2(unsigned long long v) {
    float2 r;
    asm("mov.b64 {%0, %1}, %2;" : "=f"(r.x), "=f"(r.y) : "l"(v));
    return r;
}

// ---------------- prep kernels ----------------
__global__ void vq_zero() {
    int i = blockIdx.x * blockDim.x + threadIdx.x;
    if (i < KC * DC) g_sums[i] = 0.f;
    else if (i < KC * DC + KC) g_counts[i - KC * DC] = 0.f;
    else if (i == KC * DC + KC) g_loss[0] = 0.f;
}

__global__ void vq_esq(const float* __restrict__ E) {
    int k = blockIdx.x * blockDim.x + threadIdx.x;
    if (k < KC) {
        const float4* r = (const float4*)(E + (size_t)k * DC);
        float s = 0.f;
#pragma unroll
        for (int q = 0; q < DC / 4; q++) {
            float4 v = r[q];
            s = fmaf(v.x, v.x, s); s = fmaf(v.y, v.y, s);
            s = fmaf(v.z, v.z, s); s = fmaf(v.w, v.w, s);
        }
        g_esq[k] = s;
    }
}

// ---------------- main kernel ----------------
// smem: Xs[64][130] d-major (rows contiguous, pitch 130 -> LDS.64 aligned, conflict-free),
//       Es[64][129] d-major (scalar loads, conflict-free), xsq[128]
#define XS_PITCH 130
#define ES_PITCH 129
#define SMEM_FLOATS (DC * XS_PITCH + DC * ES_PITCH + TM)

extern "C" __global__ void __launch_bounds__(256, 2)
vq_main(const float* __restrict__ X, const float* __restrict__ E,
        float* __restrict__ oZ, float* __restrict__ oArg, float* __restrict__ oMin) {
    extern __shared__ float smem[];
    float* Xs = smem;                       // DC * XS_PITCH
    float* Es = smem + DC * XS_PITCH;       // DC * ES_PITCH
    float* xsq = Es + DC * ES_PITCH;        // TM

    int tid = threadIdx.x;
    int tx = tid & 15;        // code group (codes tx + 16*j)
    int ty = tid >> 4;        // row group (rows ty*8 .. ty*8+7)

    // load X tile (coalesced gmem read, transposed store; bank = (2d+row)%32, 2-way max)
    const float* Xg = X + (size_t)blockIdx.x * TM * DC;
#pragma unroll
    for (int i = tid; i < TM * DC; i += 256) {
        int r = i >> 6, d = i & 63;
        Xs[d * XS_PITCH + r] = Xg[i];
    }
    __syncthreads();

    if (tid < TM) {
        float s = 0.f;
#pragma unroll 8
        for (int d = 0; d < DC; d++) {
            float v = Xs[d * XS_PITCH + tid];
            s = fmaf(v, v, s);
        }
        xsq[tid] = s;
    }

    float best[8];
    int bidx[8];
#pragma unroll
    for (int l = 0; l < 8; l++) { best[l] = 3.4e38f; bidx[l] = 0; }

    for (int ch = 0; ch < KC / TKC; ch++) {
        __syncthreads();   // previous chunk's Es reads done (and xsq writes on first iter)
        const float* Eg = E + (size_t)ch * TKC * DC;
#pragma unroll
        for (int i = tid; i < TKC * DC; i += 256) {
            int k = i >> 6, d = i & 63;
            Es[d * ES_PITCH + k] = Eg[i];
        }
        __syncthreads();

        unsigned long long acc[4][8];
#pragma unroll
        for (int rp = 0; rp < 4; rp++)
#pragma unroll
            for (int j = 0; j < 8; j++) acc[rp][j] = 0ull;

#pragma unroll 4
        for (int d = 0; d < DC; d++) {
            const float* xr = Xs + d * XS_PITCH + ty * 8;
            unsigned long long xp0 = *(const unsigned long long*)(xr);
            unsigned long long xp1 = *(const unsigned long long*)(xr + 2);
            unsigned long long xp2 = *(const unsigned long long*)(xr + 4);
            unsigned long long xp3 = *(const unsigned long long*)(xr + 6);
            const float* er = Es + d * ES_PITCH + tx;
#pragma unroll
            for (int j = 0; j < 8; j++) {
                float e = er[16 * j];
                unsigned long long ed = pack2(e, e);
                fma2(acc[0][j], xp0, ed);
                fma2(acc[1][j], xp1, ed);
                fma2(acc[2][j], xp2, ed);
                fma2(acc[3][j], xp3, ed);
            }
        }

        // chunk epilogue: dist-without-xsq = esq - 2*dot; strict < keeps earliest index
#pragma unroll
        for (int j = 0; j < 8; j++) {
            int c = ch * TKC + tx + 16 * j;
            float es = g_esq[c];
#pragma unroll
            for (int rp = 0; rp < 4; rp++) {
                float2 dd = unpack2(acc[rp][j]);
                float s0 = fmaf(-2.f, dd.x, es);
                float s1 = fmaf(-2.f, dd.y, es);
                if (s0 < best[2 * rp])     { best[2 * rp] = s0;     bidx[2 * rp] = c; }
                if (s1 < best[2 * rp + 1]) { best[2 * rp + 1] = s1; bidx[2 * rp + 1] = c; }
            }
        }
    }
    __syncthreads();

    // cross-thread argmin reduction (reuse Es space), pitch 17 = conflict-free scan
    float* red_d = Es;
    int* red_i = (int*)(Es + TM * 17);
#pragma unroll
    for (int l = 0; l < 8; l++) {
        int row = ty * 8 + l;
        red_d[row * 17 + tx] = best[l];
        red_i[row * 17 + tx] = bidx[l];
    }
    __syncthreads();

    if (tid < TM) {
        int row = tid;
        float bd = red_d[row * 17];
        int bi = red_i[row * 17];
#pragma unroll
        for (int t = 1; t < 16; t++) {
            float v = red_d[row * 17 + t];
            int ii = red_i[row * 17 + t];
            if (v < bd || (v == bd && ii < bi)) { bd = v; bi = ii; }
        }
        size_t gr = (size_t)blockIdx.x * TM + row;
        oMin[gr] = xsq[row] + bd;
        oArg[gr] = (float)bi;

        const float4* Er = (const float4*)(E + (size_t)bi * DC);
        float4* Zr = (float4*)(oZ + gr * DC);
        float lsum = 0.f;
        atomicAdd(&g_counts[bi], 1.0f);
        float* srow = &g_sums[bi * DC];
#pragma unroll 4
        for (int q = 0; q < DC / 4; q++) {
            float4 e4 = Er[q];
            float x0 = Xs[(4 * q + 0) * XS_PITCH + row];
            float x1 = Xs[(4 * q + 1) * XS_PITCH + row];
            float x2 = Xs[(4 * q + 2) * XS_PITCH + row];
            float x3 = Xs[(4 * q + 3) * XS_PITCH + row];
            float d0 = e4.x - x0, d1 = e4.y - x1, d2 = e4.z - x2, d3 = e4.w - x3;
            float4 z;
            z.x = x0 + d0; z.y = x1 + d1; z.z = x2 + d2; z.w = x3 + d3;  // X + (Zraw - X)
            Zr[q] = z;
            lsum = fmaf(d0, d0, lsum); lsum = fmaf(d1, d1, lsum);
            lsum = fmaf(d2, d2, lsum); lsum = fmaf(d3, d3, lsum);
            atomicAdd(srow + 4 * q + 0, x0);
            atomicAdd(srow + 4 * q + 1, x1);
            atomicAdd(srow + 4 * q + 2, x2);
            atomicAdd(srow + 4 * q + 3, x3);
        }
#pragma unroll
        for (int o = 16; o > 0; o >>= 1) lsum += __shfl_xor_sync(0xffffffffu, lsum, o);
        if ((tid & 31) == 0) atomicAdd(g_loss, lsum);
    }
}

// ---------------- finalize ----------------
__global__ void vq_finalize(const float* __restrict__ cs_in, const float* __restrict__ mavg,
                            float* __restrict__ oLoss, float* __restrict__ oEn,
                            float* __restrict__ oCs, float* __restrict__ oMa) {
    __shared__ float wsum[32];
    __shared__ float Ssh;
    int k = threadIdx.x;
    const float G = 0.99f;
    const float OMG = (float)(1.0 - 0.99);   // match reference (1.0 - GAMMA)
    float c = G * cs_in[k] + OMG * g_counts[k];

    float s = c;
#pragma unroll
    for (int o = 16; o > 0; o >>= 1) s += __shfl_xor_sync(0xffffffffu, s, o);
    if ((k & 31) == 0) wsum[k >> 5] = s;
    __syncthreads();
    if (k < 32) {
        float t = wsum[k];
#pragma unroll
        for (int o = 16; o > 0; o >>= 1) t += __shfl_xor_sync(0xffffffffu, t, o);
        if (k == 0) Ssh = t;
    }
    __syncthreads();
    float S = Ssh;

    float csa = (c + 1e-9f) / (1.0f + (float)(1e-9 * 1024.0) / S);
    oCs[k] = csa;
#pragma unroll 4
    for (int d = 0; d < DC; d++) {
        float m = G * mavg[k * DC + d] + OMG * g_sums[k * DC + d];
        oMa[k * DC + d] = m;
        oEn[k * DC + d] = m / csa;
    }
    if (k == 0) oLoss[0] = 0.25f * g_loss[0] / (float)NV;
}

// ---------------- launch ----------------
extern "C" void kernel_launch(void* const* d_in, const int* in_sizes, int n_in,
                              void* d_out, int out_size) {
    const float* X  = (const float*)d_in[0];
    const float* E  = (const float*)d_in[1];
    const float* cs = (const float*)d_in[2];
    const float* ma = (const float*)d_in[3];

    float* o = (float*)d_out;
    // output layout: Z[N*D], loss[1], argmins[N], min_dist[N], E_new[K*D], cs[K], ma[K*D]
    float* oZ    = o;
    float* oLoss = o + (size_t)NV * DC;
    float* oArg  = oLoss + 1;
    float* oMin  = oArg + NV;
    float* oEn   = oMin + NV;
    float* oCs   = oEn + (size_t)KC * DC;
    float* oMa   = oCs + KC;

    int smem = SMEM_FLOATS * 4;
    cudaFuncSetAttribute(vq_main, cudaFuncAttributeMaxDynamicSharedMemorySize, smem);

    vq_zero<<<(KC * DC + KC + 1 + 255) / 256, 256>>>();
    vq_esq<<<(KC + 255) / 256, 256>>>(E);
    vq_main<<<NV / TM, 256, smem>>>(X, E, oZ, oArg, oMin);
    vq_finalize<<<1, KC>>>(cs, ma, oLoss, oEn, oCs, oMa);
}